// round 1
// baseline (speedup 1.0000x reference)
#include <cuda_runtime.h>
#include <math.h>
#include <math_constants.h>

// Problem constants
#define BATCH   64
#define SEQ     256
#define NEMB    384
#define NHEAD   6
#define HD      64
#define BH      (BATCH*NHEAD)      // 384
#define MTOT    (BATCH*SEQ)        // 16384
#define N_QKV   (3*NEMB)           // 1152

// Scratch: per-head-layout q/k/v and attention output [B, nh, T, hd]
__device__ float g_q[BH*SEQ*HD];
__device__ float g_k[BH*SEQ*HD];
__device__ float g_v[BH*SEQ*HD];
__device__ float g_o[BH*SEQ*HD];

// ---------------------------------------------------------------------------
// Kernel 1: qkv = x @ w_attn, epilogue applies RoPE to q,k and scatters to
// [B, nh, T, hd] layout. 128x128x8 tiled sgemm, 256 threads, 8x8 per thread.
// M=16384, N=1152, K=384 (all tile-divisible, no edge handling).
// ---------------------------------------------------------------------------
__global__ __launch_bounds__(256) void qkv_gemm_rope(
    const float* __restrict__ X, const float* __restrict__ W)
{
    __shared__ __align__(16) float As[8*128];   // As[k][m] (transposed)
    __shared__ __align__(16) float Bs[8*128];   // Bs[k][n]

    const int tid = threadIdx.x;
    const int bm = blockIdx.y, bn = blockIdx.x;
    const int ty = tid >> 4, tx = tid & 15;

    const int arow = tid >> 1;            // 0..127
    const int acol = (tid & 1) * 4;       // 0 or 4
    const int brow = tid >> 5;            // 0..7
    const int bcol = (tid & 31) * 4;      // 0..124

    const float* aptr = X + (size_t)(bm*128 + arow)*NEMB + acol;
    const float* bptr = W + (size_t)brow*N_QKV + bn*128 + bcol;

    float acc[8][8];
    #pragma unroll
    for (int i = 0; i < 8; ++i)
        #pragma unroll
        for (int j = 0; j < 8; ++j) acc[i][j] = 0.f;

    for (int k0 = 0; k0 < NEMB; k0 += 8) {
        float4 av = *(const float4*)(aptr + k0);
        As[(acol+0)*128 + arow] = av.x;
        As[(acol+1)*128 + arow] = av.y;
        As[(acol+2)*128 + arow] = av.z;
        As[(acol+3)*128 + arow] = av.w;
        *(float4*)(Bs + brow*128 + bcol) =
            *(const float4*)(bptr + (size_t)k0*N_QKV);
        __syncthreads();
        #pragma unroll
        for (int k = 0; k < 8; ++k) {
            float4 a0 = *(const float4*)(As + k*128 + ty*8);
            float4 a1 = *(const float4*)(As + k*128 + ty*8 + 4);
            float4 b0 = *(const float4*)(Bs + k*128 + tx*8);
            float4 b1 = *(const float4*)(Bs + k*128 + tx*8 + 4);
            float a[8] = {a0.x,a0.y,a0.z,a0.w,a1.x,a1.y,a1.z,a1.w};
            float b[8] = {b0.x,b0.y,b0.z,b0.w,b1.x,b1.y,b1.z,b1.w};
            #pragma unroll
            for (int i = 0; i < 8; ++i)
                #pragma unroll
                for (int j = 0; j < 8; ++j)
                    acc[i][j] = fmaf(a[i], b[j], acc[i][j]);
        }
        __syncthreads();
    }

    // Epilogue. Column-block bn spans exactly one of q/k/v (384 = 3*128).
    const int nbase   = bn*128 + tx*8;      // 8 consecutive output columns
    const int section = bn / 3;             // 0=q 1=k 2=v
    const int h       = (nbase % NEMB) >> 6;
    const int dbase   = nbase & 63;         // multiple of 8 -> float4 aligned
    float* dst = (section == 0) ? g_q : (section == 1) ? g_k : g_v;

    #pragma unroll
    for (int i = 0; i < 8; ++i) {
        int m = bm*128 + ty*8 + i;
        int b = m >> 8, t = m & 255;
        size_t base = (((size_t)(b*NHEAD + h))*SEQ + t)*HD + dbase;
        if (section == 2) {
            *(float4*)(dst + base)     = make_float4(acc[i][0],acc[i][1],acc[i][2],acc[i][3]);
            *(float4*)(dst + base + 4) = make_float4(acc[i][4],acc[i][5],acc[i][6],acc[i][7]);
        } else {
            float vals[8];
            #pragma unroll
            for (int jp = 0; jp < 8; jp += 2) {
                int d = dbase + jp;                       // even
                // theta = t * 10000^(-d/64) = t * exp2(-d * log2(1e4)/64)
                float theta = (float)t *
                    exp2f((float)d * (-13.287712379549449f/64.f));
                float sn, cs;
                sincosf(theta, &sn, &cs);
                float e = acc[i][jp], o = acc[i][jp+1];
                vals[jp]   = e*cs - o*sn;
                vals[jp+1] = o*cs + e*sn;
            }
            *(float4*)(dst + base)     = make_float4(vals[0],vals[1],vals[2],vals[3]);
            *(float4*)(dst + base + 4) = make_float4(vals[4],vals[5],vals[6],vals[7]);
        }
    }
}

// ---------------------------------------------------------------------------
// Kernel 2: causal attention. One CTA per (b,h); thread i owns query row i.
// K/V streamed through SMEM in 64-row tiles; inside the j-loop all active
// lanes read the SAME key/value row -> pure SMEM broadcast, FMA-bound.
// Online (streaming) softmax per thread.
// ---------------------------------------------------------------------------
__global__ __launch_bounds__(256) void attn_kernel()
{
    __shared__ __align__(16) float Ks[64*HD];
    __shared__ __align__(16) float Vs[64*HD];

    const int bh  = blockIdx.x;
    const int row = threadIdx.x;                 // query row 0..255
    const float* Qb = g_q + (size_t)bh*SEQ*HD;
    const float* Kb = g_k + (size_t)bh*SEQ*HD;
    const float* Vb = g_v + (size_t)bh*SEQ*HD;
    float*       Ob = g_o + (size_t)bh*SEQ*HD;

    float4 q4[16];
    const float4* qrow = (const float4*)(Qb + (size_t)row*HD);
    #pragma unroll
    for (int c = 0; c < 16; ++c) q4[c] = qrow[c];

    float4 acc[16];
    #pragma unroll
    for (int c = 0; c < 16; ++c) acc[c] = make_float4(0.f,0.f,0.f,0.f);
    float mmax = -CUDART_INF_F;
    float lsum = 0.f;

    for (int kt = 0; kt < SEQ/64; ++kt) {
        // cooperative tile load: 64x64 floats = 1024 float4, 4 per thread
        const float4* ksrc = (const float4*)(Kb + (size_t)kt*64*HD);
        const float4* vsrc = (const float4*)(Vb + (size_t)kt*64*HD);
        #pragma unroll
        for (int u = 0; u < 4; ++u) {
            ((float4*)Ks)[threadIdx.x + 256*u] = ksrc[threadIdx.x + 256*u];
            ((float4*)Vs)[threadIdx.x + 256*u] = vsrc[threadIdx.x + 256*u];
        }
        __syncthreads();

        int jmax = row - kt*64; if (jmax > 63) jmax = 63;
        for (int jj = 0; jj <= jmax; ++jj) {
            const float4* k4 = (const float4*)(Ks + jj*HD);
            float s0=0.f, s1=0.f, s2=0.f, s3=0.f;   // 4 chains for ILP
            #pragma unroll
            for (int c = 0; c < 16; ++c) {
                float4 kv = k4[c];
                s0 = fmaf(q4[c].x, kv.x, s0);
                s1 = fmaf(q4[c].y, kv.y, s1);
                s2 = fmaf(q4[c].z, kv.z, s2);
                s3 = fmaf(q4[c].w, kv.w, s3);
            }
            float s = ((s0+s1)+(s2+s3)) * 0.125f;   // scale = hd^-0.5

            float p;
            if (s > mmax) {
                float corr = exp2f((mmax - s) * 1.4426950408889634f);
                lsum *= corr;
                #pragma unroll
                for (int c = 0; c < 16; ++c) {
                    acc[c].x *= corr; acc[c].y *= corr;
                    acc[c].z *= corr; acc[c].w *= corr;
                }
                mmax = s;
                p = 1.0f;
            } else {
                p = exp2f((s - mmax) * 1.4426950408889634f);
            }
            lsum += p;

            const float4* v4 = (const float4*)(Vs + jj*HD);
            #pragma unroll
            for (int c = 0; c < 16; ++c) {
                float4 vv = v4[c];
                acc[c].x = fmaf(p, vv.x, acc[c].x);
                acc[c].y = fmaf(p, vv.y, acc[c].y);
                acc[c].z = fmaf(p, vv.z, acc[c].z);
                acc[c].w = fmaf(p, vv.w, acc[c].w);
            }
        }
        __syncthreads();
    }

    float inv = 1.0f / lsum;
    float4* orow = (float4*)(Ob + (size_t)row*HD);
    #pragma unroll
    for (int c = 0; c < 16; ++c)
        orow[c] = make_float4(acc[c].x*inv, acc[c].y*inv,
                              acc[c].z*inv, acc[c].w*inv);
}

// ---------------------------------------------------------------------------
// Kernel 3: out = attn_out(gathered [B,T,nh*hd]) @ w_proj. Same sgemm shape,
// A-tile load gathers the head-transpose. M=16384, N=384, K=384.
// ---------------------------------------------------------------------------
__global__ __launch_bounds__(256) void proj_gemm(
    const float* __restrict__ W, float* __restrict__ out)
{
    __shared__ __align__(16) float As[8*128];
    __shared__ __align__(16) float Bs[8*128];

    const int tid = threadIdx.x;
    const int bm = blockIdx.y, bn = blockIdx.x;
    const int ty = tid >> 4, tx = tid & 15;

    const int arow = tid >> 1;
    const int acol = (tid & 1) * 4;
    const int brow = tid >> 5;
    const int bcol = (tid & 31) * 4;

    const int m_a = bm*128 + arow;
    const int b_a = m_a >> 8, t_a = m_a & 255;
    const float* bptr = W + (size_t)brow*NEMB + bn*128 + bcol;

    float acc[8][8];
    #pragma unroll
    for (int i = 0; i < 8; ++i)
        #pragma unroll
        for (int j = 0; j < 8; ++j) acc[i][j] = 0.f;

    for (int k0 = 0; k0 < NEMB; k0 += 8) {
        int kk = k0 + acol;                 // multiple of 4, within one head
        int h = kk >> 6, d = kk & 63;
        float4 av = *(const float4*)(g_o +
            (((size_t)(b_a*NHEAD + h))*SEQ + t_a)*HD + d);
        As[(acol+0)*128 + arow] = av.x;
        As[(acol+1)*128 + arow] = av.y;
        As[(acol+2)*128 + arow] = av.z;
        As[(acol+3)*128 + arow] = av.w;
        *(float4*)(Bs + brow*128 + bcol) =
            *(const float4*)(bptr + (size_t)k0*NEMB);
        __syncthreads();
        #pragma unroll
        for (int k = 0; k < 8; ++k) {
            float4 a0 = *(const float4*)(As + k*128 + ty*8);
            float4 a1 = *(const float4*)(As + k*128 + ty*8 + 4);
            float4 b0 = *(const float4*)(Bs + k*128 + tx*8);
            float4 b1 = *(const float4*)(Bs + k*128 + tx*8 + 4);
            float a[8] = {a0.x,a0.y,a0.z,a0.w,a1.x,a1.y,a1.z,a1.w};
            float b[8] = {b0.x,b0.y,b0.z,b0.w,b1.x,b1.y,b1.z,b1.w};
            #pragma unroll
            for (int i = 0; i < 8; ++i)
                #pragma unroll
                for (int j = 0; j < 8; ++j)
                    acc[i][j] = fmaf(a[i], b[j], acc[i][j]);
        }
        __syncthreads();
    }

    const int nbase = bn*128 + tx*8;
    #pragma unroll
    for (int i = 0; i < 8; ++i) {
        int m = bm*128 + ty*8 + i;
        float* dst = out + (size_t)m*NEMB + nbase;
        *(float4*)(dst)     = make_float4(acc[i][0],acc[i][1],acc[i][2],acc[i][3]);
        *(float4*)(dst + 4) = make_float4(acc[i][4],acc[i][5],acc[i][6],acc[i][7]);
    }
}

// ---------------------------------------------------------------------------
extern "C" void kernel_launch(void* const* d_in, const int* in_sizes, int n_in,
                              void* d_out, int out_size)
{
    const float* x      = (const float*)d_in[0];   // [64,256,384]
    const float* w_attn = (const float*)d_in[1];   // [384,1152]
    const float* w_proj = (const float*)d_in[2];   // [384,384]
    float* out = (float*)d_out;                    // [64,256,384]

    dim3 g1(N_QKV/128, MTOT/128);   // (9, 128)
    qkv_gemm_rope<<<g1, 256>>>(x, w_attn);

    attn_kernel<<<BH, 256>>>();

    dim3 g3(NEMB/128, MTOT/128);    // (3, 128)
    proj_gemm<<<g3, 256>>>(w_proj, out);
}

// round 2
// speedup vs baseline: 1.6215x; 1.6215x over previous
#include <cuda_runtime.h>
#include <math.h>
#include <math_constants.h>

// Problem constants
#define BATCH   64
#define SEQ     256
#define NEMB    384
#define NHEAD   6
#define HD      64
#define BH      (BATCH*NHEAD)      // 384
#define MTOT    (BATCH*SEQ)        // 16384
#define N_QKV   (3*NEMB)           // 1152

#define KC  16          // k-chunk per smem stage
#define PK  20          // As pitch (16 + 4 pad) -> conflict-free frag loads
#define PN  136         // Bs pitch (128 + 8 pad) -> conflict-free frag loads

// Scratch: per-head-layout q/k/v and attention output [B, nh, T, hd]
__device__ float g_q[BH*SEQ*HD];
__device__ float g_k[BH*SEQ*HD];
__device__ float g_v[BH*SEQ*HD];
__device__ float g_o[BH*SEQ*HD];

__device__ __forceinline__ unsigned f2tf(float f) {
    unsigned u;
    asm("cvt.rna.tf32.f32 %0, %1;" : "=r"(u) : "f"(f));
    return u;
}

__device__ __forceinline__ void mma8(float* c, const unsigned* a, const unsigned* b) {
    asm volatile(
        "mma.sync.aligned.m16n8k8.row.col.f32.tf32.tf32.f32 "
        "{%0,%1,%2,%3}, {%4,%5,%6,%7}, {%8,%9}, {%0,%1,%2,%3};"
        : "+f"(c[0]), "+f"(c[1]), "+f"(c[2]), "+f"(c[3])
        : "r"(a[0]), "r"(a[1]), "r"(a[2]), "r"(a[3]),
          "r"(b[0]), "r"(b[1]));
}

// ---------------------------------------------------------------------------
// Kernel 1: qkv = x @ w_attn via tf32 mma.sync; epilogue applies RoPE to q,k
// and scatters to [B, nh, T, hd]. CTA tile 128x128, kc=16, 8 warps of 64x32.
// ---------------------------------------------------------------------------
__global__ __launch_bounds__(256) void qkv_gemm_rope(
    const float* __restrict__ X, const float* __restrict__ W)
{
    __shared__ __align__(16) unsigned As[128*PK];
    __shared__ __align__(16) unsigned Bs[KC*PN];

    const int tid  = threadIdx.x;
    const int lane = tid & 31;
    const int w    = tid >> 5;
    const int wm   = w >> 2;        // 0..1
    const int wn   = w & 3;         // 0..3
    const int g    = lane >> 2;     // 0..7
    const int t    = lane & 3;      // 0..3
    const int bm   = blockIdx.y, bn = blockIdx.x;

    // gmem load assignment
    const int am  = tid >> 1;          // 0..127
    const int akq = (tid & 1) * 8;     // 0 or 8
    const int bkr = tid >> 4;          // 0..15
    const int bnq = (tid & 15) * 8;    // 0..120
    const float* aptr = X + (size_t)(bm*128 + am)*NEMB + akq;
    const float* bptr = W + (size_t)bkr*N_QKV + bn*128 + bnq;

    float acc[4][4][4];
    #pragma unroll
    for (int i = 0; i < 4; ++i)
        #pragma unroll
        for (int j = 0; j < 4; ++j)
            #pragma unroll
            for (int q = 0; q < 4; ++q) acc[i][j][q] = 0.f;

    unsigned ra[8], rb[8];
    {   // prefetch chunk 0
        float4 x0 = *(const float4*)(aptr);
        float4 x1 = *(const float4*)(aptr + 4);
        ra[0]=f2tf(x0.x); ra[1]=f2tf(x0.y); ra[2]=f2tf(x0.z); ra[3]=f2tf(x0.w);
        ra[4]=f2tf(x1.x); ra[5]=f2tf(x1.y); ra[6]=f2tf(x1.z); ra[7]=f2tf(x1.w);
        float4 b0 = *(const float4*)(bptr);
        float4 b1 = *(const float4*)(bptr + 4);
        rb[0]=f2tf(b0.x); rb[1]=f2tf(b0.y); rb[2]=f2tf(b0.z); rb[3]=f2tf(b0.w);
        rb[4]=f2tf(b1.x); rb[5]=f2tf(b1.y); rb[6]=f2tf(b1.z); rb[7]=f2tf(b1.w);
    }

    for (int c = 0; c < NEMB/KC; ++c) {
        *(uint4*)(As + am*PK + akq)     = make_uint4(ra[0],ra[1],ra[2],ra[3]);
        *(uint4*)(As + am*PK + akq + 4) = make_uint4(ra[4],ra[5],ra[6],ra[7]);
        *(uint4*)(Bs + bkr*PN + bnq)     = make_uint4(rb[0],rb[1],rb[2],rb[3]);
        *(uint4*)(Bs + bkr*PN + bnq + 4) = make_uint4(rb[4],rb[5],rb[6],rb[7]);
        __syncthreads();

        if (c + 1 < NEMB/KC) {
            const float* ap = aptr + (c+1)*KC;
            float4 x0 = *(const float4*)(ap);
            float4 x1 = *(const float4*)(ap + 4);
            ra[0]=f2tf(x0.x); ra[1]=f2tf(x0.y); ra[2]=f2tf(x0.z); ra[3]=f2tf(x0.w);
            ra[4]=f2tf(x1.x); ra[5]=f2tf(x1.y); ra[6]=f2tf(x1.z); ra[7]=f2tf(x1.w);
            const float* bp = bptr + (size_t)(c+1)*KC*N_QKV;
            float4 b0 = *(const float4*)(bp);
            float4 b1 = *(const float4*)(bp + 4);
            rb[0]=f2tf(b0.x); rb[1]=f2tf(b0.y); rb[2]=f2tf(b0.z); rb[3]=f2tf(b0.w);
            rb[4]=f2tf(b1.x); rb[5]=f2tf(b1.y); rb[6]=f2tf(b1.z); rb[7]=f2tf(b1.w);
        }

        #pragma unroll
        for (int ks = 0; ks < 2; ++ks) {
            unsigned af[4][4], bf[4][2];
            const int kk = ks*8 + t;
            #pragma unroll
            for (int mf = 0; mf < 4; ++mf) {
                int r = wm*64 + mf*16 + g;
                af[mf][0] = As[r*PK + kk];
                af[mf][1] = As[(r+8)*PK + kk];
                af[mf][2] = As[r*PK + kk + 4];
                af[mf][3] = As[(r+8)*PK + kk + 4];
            }
            #pragma unroll
            for (int nf = 0; nf < 4; ++nf) {
                int n = wn*32 + nf*8 + g;
                bf[nf][0] = Bs[kk*PN + n];
                bf[nf][1] = Bs[(kk+4)*PN + n];
            }
            #pragma unroll
            for (int mf = 0; mf < 4; ++mf)
                #pragma unroll
                for (int nf = 0; nf < 4; ++nf)
                    mma8(acc[mf][nf], af[mf], bf[nf]);
        }
        __syncthreads();
    }

    // Epilogue: scatter + RoPE. bn spans exactly one of q/k/v (3 bn each).
    const int section = bn / 3;  // 0=q 1=k 2=v
    float* dst = (section == 0) ? g_q : (section == 1) ? g_k : g_v;
    const int ncol0 = (bn % 3) * 128;

    // d depends only on nf (and lane t); precompute inv freq
    float invf[4];
    #pragma unroll
    for (int nf = 0; nf < 4; ++nf) {
        int d = (ncol0 + wn*32 + nf*8 + 2*t) & 63;   // even
        invf[nf] = exp2f((float)d * (-13.287712379549449f/64.f));
    }

    #pragma unroll
    for (int mf = 0; mf < 4; ++mf) {
        int r0 = bm*128 + wm*64 + mf*16 + g;
        #pragma unroll
        for (int half = 0; half < 2; ++half) {
            int row = r0 + 8*half;
            int b = row >> 8, tt = row & 255;
            #pragma unroll
            for (int nf = 0; nf < 4; ++nf) {
                int nn = ncol0 + wn*32 + nf*8 + 2*t;
                int h = nn >> 6, d = nn & 63;
                size_t base = (((size_t)(b*NHEAD + h))*SEQ + tt)*HD + d;
                float e = acc[mf][nf][2*half];
                float o = acc[mf][nf][2*half + 1];
                if (section == 2) {
                    *(float2*)(dst + base) = make_float2(e, o);
                } else {
                    float theta = (float)tt * invf[nf];
                    float sn, cs;
                    sincosf(theta, &sn, &cs);
                    *(float2*)(dst + base) =
                        make_float2(e*cs - o*sn, o*cs + e*sn);
                }
            }
        }
    }
}

// ---------------------------------------------------------------------------
// Kernel 2: causal attention (unchanged fp32 path). One CTA per (b,h);
// thread i owns query row i; K/V streamed via SMEM broadcast; online softmax.
// ---------------------------------------------------------------------------
__global__ __launch_bounds__(256) void attn_kernel()
{
    __shared__ __align__(16) float Ks[64*HD];
    __shared__ __align__(16) float Vs[64*HD];

    const int bh  = blockIdx.x;
    const int row = threadIdx.x;
    const float* Qb = g_q + (size_t)bh*SEQ*HD;
    const float* Kb = g_k + (size_t)bh*SEQ*HD;
    const float* Vb = g_v + (size_t)bh*SEQ*HD;
    float*       Ob = g_o + (size_t)bh*SEQ*HD;

    float4 q4[16];
    const float4* qrow = (const float4*)(Qb + (size_t)row*HD);
    #pragma unroll
    for (int c = 0; c < 16; ++c) q4[c] = qrow[c];

    float4 acc[16];
    #pragma unroll
    for (int c = 0; c < 16; ++c) acc[c] = make_float4(0.f,0.f,0.f,0.f);
    float mmax = -CUDART_INF_F;
    float lsum = 0.f;

    for (int kt = 0; kt < SEQ/64; ++kt) {
        const float4* ksrc = (const float4*)(Kb + (size_t)kt*64*HD);
        const float4* vsrc = (const float4*)(Vb + (size_t)kt*64*HD);
        #pragma unroll
        for (int u = 0; u < 4; ++u) {
            ((float4*)Ks)[threadIdx.x + 256*u] = ksrc[threadIdx.x + 256*u];
            ((float4*)Vs)[threadIdx.x + 256*u] = vsrc[threadIdx.x + 256*u];
        }
        __syncthreads();

        int jmax = row - kt*64; if (jmax > 63) jmax = 63;
        for (int jj = 0; jj <= jmax; ++jj) {
            const float4* k4 = (const float4*)(Ks + jj*HD);
            float s0=0.f, s1=0.f, s2=0.f, s3=0.f;
            #pragma unroll
            for (int c = 0; c < 16; ++c) {
                float4 kv = k4[c];
                s0 = fmaf(q4[c].x, kv.x, s0);
                s1 = fmaf(q4[c].y, kv.y, s1);
                s2 = fmaf(q4[c].z, kv.z, s2);
                s3 = fmaf(q4[c].w, kv.w, s3);
            }
            float s = ((s0+s1)+(s2+s3)) * 0.125f;

            float p;
            if (s > mmax) {
                float corr = exp2f((mmax - s) * 1.4426950408889634f);
                lsum *= corr;
                #pragma unroll
                for (int c = 0; c < 16; ++c) {
                    acc[c].x *= corr; acc[c].y *= corr;
                    acc[c].z *= corr; acc[c].w *= corr;
                }
                mmax = s;
                p = 1.0f;
            } else {
                p = exp2f((s - mmax) * 1.4426950408889634f);
            }
            lsum += p;

            const float4* v4 = (const float4*)(Vs + jj*HD);
            #pragma unroll
            for (int c = 0; c < 16; ++c) {
                float4 vv = v4[c];
                acc[c].x = fmaf(p, vv.x, acc[c].x);
                acc[c].y = fmaf(p, vv.y, acc[c].y);
                acc[c].z = fmaf(p, vv.z, acc[c].z);
                acc[c].w = fmaf(p, vv.w, acc[c].w);
            }
        }
        __syncthreads();
    }

    float inv = 1.0f / lsum;
    float4* orow = (float4*)(Ob + (size_t)row*HD);
    #pragma unroll
    for (int c = 0; c < 16; ++c)
        orow[c] = make_float4(acc[c].x*inv, acc[c].y*inv,
                              acc[c].z*inv, acc[c].w*inv);
}

// ---------------------------------------------------------------------------
// Kernel 3: out = attn_out(gathered [B,T,C]) @ w_proj via tf32 mma.sync.
// Same GEMM core; A-tile load gathers the head-transpose from g_o.
// ---------------------------------------------------------------------------
__global__ __launch_bounds__(256) void proj_gemm(
    const float* __restrict__ W, float* __restrict__ out)
{
    __shared__ __align__(16) unsigned As[128*PK];
    __shared__ __align__(16) unsigned Bs[KC*PN];

    const int tid  = threadIdx.x;
    const int lane = tid & 31;
    const int w    = tid >> 5;
    const int wm   = w >> 2;
    const int wn   = w & 3;
    const int g    = lane >> 2;
    const int t    = lane & 3;
    const int bm   = blockIdx.y, bn = blockIdx.x;

    const int am  = tid >> 1;
    const int akq = (tid & 1) * 8;
    const int bkr = tid >> 4;
    const int bnq = (tid & 15) * 8;

    const int m_a = bm*128 + am;
    const int b_a = m_a >> 8, t_a = m_a & 255;
    const float* bptr = W + (size_t)bkr*NEMB + bn*128 + bnq;

    float acc[4][4][4];
    #pragma unroll
    for (int i = 0; i < 4; ++i)
        #pragma unroll
        for (int j = 0; j < 4; ++j)
            #pragma unroll
            for (int q = 0; q < 4; ++q) acc[i][j][q] = 0.f;

    unsigned ra[8], rb[8];
    {
        int kk = akq;                       // chunk 0
        int h = kk >> 6, d = kk & 63;
        const float* ap = g_o + (((size_t)(b_a*NHEAD + h))*SEQ + t_a)*HD + d;
        float4 x0 = *(const float4*)(ap);
        float4 x1 = *(const float4*)(ap + 4);
        ra[0]=f2tf(x0.x); ra[1]=f2tf(x0.y); ra[2]=f2tf(x0.z); ra[3]=f2tf(x0.w);
        ra[4]=f2tf(x1.x); ra[5]=f2tf(x1.y); ra[6]=f2tf(x1.z); ra[7]=f2tf(x1.w);
        float4 b0 = *(const float4*)(bptr);
        float4 b1 = *(const float4*)(bptr + 4);
        rb[0]=f2tf(b0.x); rb[1]=f2tf(b0.y); rb[2]=f2tf(b0.z); rb[3]=f2tf(b0.w);
        rb[4]=f2tf(b1.x); rb[5]=f2tf(b1.y); rb[6]=f2tf(b1.z); rb[7]=f2tf(b1.w);
    }

    for (int c = 0; c < NEMB/KC; ++c) {
        *(uint4*)(As + am*PK + akq)     = make_uint4(ra[0],ra[1],ra[2],ra[3]);
        *(uint4*)(As + am*PK + akq + 4) = make_uint4(ra[4],ra[5],ra[6],ra[7]);
        *(uint4*)(Bs + bkr*PN + bnq)     = make_uint4(rb[0],rb[1],rb[2],rb[3]);
        *(uint4*)(Bs + bkr*PN + bnq + 4) = make_uint4(rb[4],rb[5],rb[6],rb[7]);
        __syncthreads();

        if (c + 1 < NEMB/KC) {
            int kk = (c+1)*KC + akq;
            int h = kk >> 6, d = kk & 63;
            const float* ap = g_o + (((size_t)(b_a*NHEAD + h))*SEQ + t_a)*HD + d;
            float4 x0 = *(const float4*)(ap);
            float4 x1 = *(const float4*)(ap + 4);
            ra[0]=f2tf(x0.x); ra[1]=f2tf(x0.y); ra[2]=f2tf(x0.z); ra[3]=f2tf(x0.w);
            ra[4]=f2tf(x1.x); ra[5]=f2tf(x1.y); ra[6]=f2tf(x1.z); ra[7]=f2tf(x1.w);
            const float* bp = bptr + (size_t)(c+1)*KC*NEMB;
            float4 b0 = *(const float4*)(bp);
            float4 b1 = *(const float4*)(bp + 4);
            rb[0]=f2tf(b0.x); rb[1]=f2tf(b0.y); rb[2]=f2tf(b0.z); rb[3]=f2tf(b0.w);
            rb[4]=f2tf(b1.x); rb[5]=f2tf(b1.y); rb[6]=f2tf(b1.z); rb[7]=f2tf(b1.w);
        }

        #pragma unroll
        for (int ks = 0; ks < 2; ++ks) {
            unsigned af[4][4], bf[4][2];
            const int kk = ks*8 + t;
            #pragma unroll
            for (int mf = 0; mf < 4; ++mf) {
                int r = wm*64 + mf*16 + g;
                af[mf][0] = As[r*PK + kk];
                af[mf][1] = As[(r+8)*PK + kk];
                af[mf][2] = As[r*PK + kk + 4];
                af[mf][3] = As[(r+8)*PK + kk + 4];
            }
            #pragma unroll
            for (int nf = 0; nf < 4; ++nf) {
                int n = wn*32 + nf*8 + g;
                bf[nf][0] = Bs[kk*PN + n];
                bf[nf][1] = Bs[(kk+4)*PN + n];
            }
            #pragma unroll
            for (int mf = 0; mf < 4; ++mf)
                #pragma unroll
                for (int nf = 0; nf < 4; ++nf)
                    mma8(acc[mf][nf], af[mf], bf[nf]);
        }
        __syncthreads();
    }

    #pragma unroll
    for (int mf = 0; mf < 4; ++mf) {
        int r0 = bm*128 + wm*64 + mf*16 + g;
        #pragma unroll
        for (int half = 0; half < 2; ++half) {
            int row = r0 + 8*half;
            #pragma unroll
            for (int nf = 0; nf < 4; ++nf) {
                int nn = bn*128 + wn*32 + nf*8 + 2*t;
                *(float2*)(out + (size_t)row*NEMB + nn) =
                    make_float2(acc[mf][nf][2*half], acc[mf][nf][2*half+1]);
            }
        }
    }
}

// ---------------------------------------------------------------------------
extern "C" void kernel_launch(void* const* d_in, const int* in_sizes, int n_in,
                              void* d_out, int out_size)
{
    const float* x      = (const float*)d_in[0];   // [64,256,384]
    const float* w_attn = (const float*)d_in[1];   // [384,1152]
    const float* w_proj = (const float*)d_in[2];   // [384,384]
    float* out = (float*)d_out;                    // [64,256,384]

    dim3 g1(N_QKV/128, MTOT/128);   // (9, 128)
    qkv_gemm_rope<<<g1, 256>>>(x, w_attn);

    attn_kernel<<<BH, 256>>>();

    dim3 g3(NEMB/128, MTOT/128);    // (3, 128)
    proj_gemm<<<g3, 256>>>(w_proj, out);
}

// round 3
// speedup vs baseline: 2.7634x; 1.7042x over previous
#include <cuda_runtime.h>
#include <math.h>
#include <math_constants.h>

// Problem constants
#define BATCH   64
#define SEQ     256
#define NEMB    384
#define NHEAD   6
#define HD      64
#define BH      (BATCH*NHEAD)      // 384
#define MTOT    (BATCH*SEQ)        // 16384
#define N_QKV   (3*NEMB)           // 1152

#define KC  16          // k-chunk per smem stage (gemm)
#define PK  20          // As pitch
#define PN  136         // Bs pitch

#define L2E 1.4426950408889634f

// Scratch: per-head-layout q/k/v and attention output [B, nh, T, hd]
__device__ float g_q[BH*SEQ*HD];
__device__ float g_k[BH*SEQ*HD];
__device__ float g_v[BH*SEQ*HD];
__device__ float g_o[BH*SEQ*HD];

__device__ __forceinline__ unsigned f2tf(float f) {
    unsigned u;
    asm("cvt.rna.tf32.f32 %0, %1;" : "=r"(u) : "f"(f));
    return u;
}

__device__ __forceinline__ void mma8(float* c, const unsigned* a, const unsigned* b) {
    asm volatile(
        "mma.sync.aligned.m16n8k8.row.col.f32.tf32.tf32.f32 "
        "{%0,%1,%2,%3}, {%4,%5,%6,%7}, {%8,%9}, {%0,%1,%2,%3};"
        : "+f"(c[0]), "+f"(c[1]), "+f"(c[2]), "+f"(c[3])
        : "r"(a[0]), "r"(a[1]), "r"(a[2]), "r"(a[3]),
          "r"(b[0]), "r"(b[1]));
}

// ---------------------------------------------------------------------------
// Kernel 1: qkv = x @ w_attn via tf32 mma.sync; epilogue RoPE + scatter.
// ---------------------------------------------------------------------------
__global__ __launch_bounds__(256) void qkv_gemm_rope(
    const float* __restrict__ X, const float* __restrict__ W)
{
    __shared__ __align__(16) unsigned As[128*PK];
    __shared__ __align__(16) unsigned Bs[KC*PN];

    const int tid  = threadIdx.x;
    const int lane = tid & 31;
    const int w    = tid >> 5;
    const int wm   = w >> 2;
    const int wn   = w & 3;
    const int g    = lane >> 2;
    const int t    = lane & 3;
    const int bm   = blockIdx.y, bn = blockIdx.x;

    const int am  = tid >> 1;
    const int akq = (tid & 1) * 8;
    const int bkr = tid >> 4;
    const int bnq = (tid & 15) * 8;
    const float* aptr = X + (size_t)(bm*128 + am)*NEMB + akq;
    const float* bptr = W + (size_t)bkr*N_QKV + bn*128 + bnq;

    float acc[4][4][4];
    #pragma unroll
    for (int i = 0; i < 4; ++i)
        #pragma unroll
        for (int j = 0; j < 4; ++j)
            #pragma unroll
            for (int q = 0; q < 4; ++q) acc[i][j][q] = 0.f;

    unsigned ra[8], rb[8];
    {
        float4 x0 = *(const float4*)(aptr);
        float4 x1 = *(const float4*)(aptr + 4);
        ra[0]=f2tf(x0.x); ra[1]=f2tf(x0.y); ra[2]=f2tf(x0.z); ra[3]=f2tf(x0.w);
        ra[4]=f2tf(x1.x); ra[5]=f2tf(x1.y); ra[6]=f2tf(x1.z); ra[7]=f2tf(x1.w);
        float4 b0 = *(const float4*)(bptr);
        float4 b1 = *(const float4*)(bptr + 4);
        rb[0]=f2tf(b0.x); rb[1]=f2tf(b0.y); rb[2]=f2tf(b0.z); rb[3]=f2tf(b0.w);
        rb[4]=f2tf(b1.x); rb[5]=f2tf(b1.y); rb[6]=f2tf(b1.z); rb[7]=f2tf(b1.w);
    }

    for (int c = 0; c < NEMB/KC; ++c) {
        *(uint4*)(As + am*PK + akq)     = make_uint4(ra[0],ra[1],ra[2],ra[3]);
        *(uint4*)(As + am*PK + akq + 4) = make_uint4(ra[4],ra[5],ra[6],ra[7]);
        *(uint4*)(Bs + bkr*PN + bnq)     = make_uint4(rb[0],rb[1],rb[2],rb[3]);
        *(uint4*)(Bs + bkr*PN + bnq + 4) = make_uint4(rb[4],rb[5],rb[6],rb[7]);
        __syncthreads();

        if (c + 1 < NEMB/KC) {
            const float* ap = aptr + (c+1)*KC;
            float4 x0 = *(const float4*)(ap);
            float4 x1 = *(const float4*)(ap + 4);
            ra[0]=f2tf(x0.x); ra[1]=f2tf(x0.y); ra[2]=f2tf(x0.z); ra[3]=f2tf(x0.w);
            ra[4]=f2tf(x1.x); ra[5]=f2tf(x1.y); ra[6]=f2tf(x1.z); ra[7]=f2tf(x1.w);
            const float* bp = bptr + (size_t)(c+1)*KC*N_QKV;
            float4 b0 = *(const float4*)(bp);
            float4 b1 = *(const float4*)(bp + 4);
            rb[0]=f2tf(b0.x); rb[1]=f2tf(b0.y); rb[2]=f2tf(b0.z); rb[3]=f2tf(b0.w);
            rb[4]=f2tf(b1.x); rb[5]=f2tf(b1.y); rb[6]=f2tf(b1.z); rb[7]=f2tf(b1.w);
        }

        #pragma unroll
        for (int ks = 0; ks < 2; ++ks) {
            unsigned af[4][4], bf[4][2];
            const int kk = ks*8 + t;
            #pragma unroll
            for (int mf = 0; mf < 4; ++mf) {
                int r = wm*64 + mf*16 + g;
                af[mf][0] = As[r*PK + kk];
                af[mf][1] = As[(r+8)*PK + kk];
                af[mf][2] = As[r*PK + kk + 4];
                af[mf][3] = As[(r+8)*PK + kk + 4];
            }
            #pragma unroll
            for (int nf = 0; nf < 4; ++nf) {
                int n = wn*32 + nf*8 + g;
                bf[nf][0] = Bs[kk*PN + n];
                bf[nf][1] = Bs[(kk+4)*PN + n];
            }
            #pragma unroll
            for (int mf = 0; mf < 4; ++mf)
                #pragma unroll
                for (int nf = 0; nf < 4; ++nf)
                    mma8(acc[mf][nf], af[mf], bf[nf]);
        }
        __syncthreads();
    }

    const int section = bn / 3;  // 0=q 1=k 2=v
    float* dst = (section == 0) ? g_q : (section == 1) ? g_k : g_v;
    const int ncol0 = (bn % 3) * 128;

    float invf[4];
    #pragma unroll
    for (int nf = 0; nf < 4; ++nf) {
        int d = (ncol0 + wn*32 + nf*8 + 2*t) & 63;
        invf[nf] = exp2f((float)d * (-13.287712379549449f/64.f));
    }

    #pragma unroll
    for (int mf = 0; mf < 4; ++mf) {
        int r0 = bm*128 + wm*64 + mf*16 + g;
        #pragma unroll
        for (int half = 0; half < 2; ++half) {
            int row = r0 + 8*half;
            int b = row >> 8, tt = row & 255;
            #pragma unroll
            for (int nf = 0; nf < 4; ++nf) {
                int nn = ncol0 + wn*32 + nf*8 + 2*t;
                int h = nn >> 6, d = nn & 63;
                size_t base = (((size_t)(b*NHEAD + h))*SEQ + tt)*HD + d;
                float e = acc[mf][nf][2*half];
                float o = acc[mf][nf][2*half + 1];
                if (section == 2) {
                    *(float2*)(dst + base) = make_float2(e, o);
                } else {
                    float theta = (float)tt * invf[nf];
                    float sn, cs;
                    sincosf(theta, &sn, &cs);
                    *(float2*)(dst + base) =
                        make_float2(e*cs - o*sn, o*cs + e*sn);
                }
            }
        }
    }
}

// ---------------------------------------------------------------------------
// Kernel 2: tensor-core causal flash attention (tf32 mma).
// Grid (BH, 2): CTA = one (b,h) x 128 query rows. 8 warps x 16 rows each.
// Key tiles of 32; K/V staged in SMEM (tf32), P round-trips per-warp SMEM.
// ---------------------------------------------------------------------------
__global__ __launch_bounds__(256) void attn_mma()
{
    __shared__ __align__(16) unsigned Ks[32*68];      // [key][hd]   pitch 68
    __shared__ __align__(16) unsigned Vs[32*72];      // [key][hd]   pitch 72
    __shared__ __align__(16) unsigned Ps[8*16*36];    // per-warp P  pitch 36

    const int tid  = threadIdx.x;
    const int lane = tid & 31;
    const int w    = tid >> 5;
    const int g    = lane >> 2;
    const int t    = lane & 3;
    const int bh   = blockIdx.x;
    const int qb   = blockIdx.y;

    const float* Qp = g_q + (size_t)bh*SEQ*HD;
    const float* Kp = g_k + (size_t)bh*SEQ*HD;
    const float* Vp = g_v + (size_t)bh*SEQ*HD;
    float*       Op = g_o + (size_t)bh*SEQ*HD;

    const int qrow0 = qb*128 + w*16;
    const int r0 = qrow0 + g, r1 = qrow0 + g + 8;

    // Q as tf32 A-fragments (8 k-steps over hd=64)
    unsigned qf[8][4];
    #pragma unroll
    for (int ks = 0; ks < 8; ++ks) {
        qf[ks][0] = f2tf(Qp[(size_t)r0*HD + ks*8 + t]);
        qf[ks][1] = f2tf(Qp[(size_t)r1*HD + ks*8 + t]);
        qf[ks][2] = f2tf(Qp[(size_t)r0*HD + ks*8 + t + 4]);
        qf[ks][3] = f2tf(Qp[(size_t)r1*HD + ks*8 + t + 4]);
    }

    float o[8][4];
    #pragma unroll
    for (int n = 0; n < 8; ++n)
        #pragma unroll
        for (int q = 0; q < 4; ++q) o[n][q] = 0.f;
    float m0 = -CUDART_INF_F, m1 = -CUDART_INF_F;
    float l0 = 0.f, l1 = 0.f;

    const int ntiles = qb*4 + 4;
    unsigned* Pw = Ps + w*16*36;

    for (int kt = 0; kt < ntiles; ++kt) {
        // cooperative tile load: K,V 32x64 floats each -> tf32 smem
        #pragma unroll
        for (int u = 0; u < 2; ++u) {
            int i = tid + 256*u;               // 0..511 float4 slots
            int row = i >> 4, c4 = (i & 15) * 4;
            const float* kp = Kp + (size_t)(kt*32 + row)*HD + c4;
            float4 k4 = *(const float4*)kp;
            *(uint4*)(Ks + row*68 + c4) =
                make_uint4(f2tf(k4.x), f2tf(k4.y), f2tf(k4.z), f2tf(k4.w));
            const float* vp = Vp + (size_t)(kt*32 + row)*HD + c4;
            float4 v4 = *(const float4*)vp;
            *(uint4*)(Vs + row*72 + c4) =
                make_uint4(f2tf(v4.x), f2tf(v4.y), f2tf(v4.z), f2tf(v4.w));
        }
        __syncthreads();

        if (kt*32 <= qrow0 + 15) {
            // S = Q @ K^T  (16 x 32 per warp)
            float s[4][4];
            #pragma unroll
            for (int nt = 0; nt < 4; ++nt)
                #pragma unroll
                for (int q = 0; q < 4; ++q) s[nt][q] = 0.f;
            #pragma unroll
            for (int ks = 0; ks < 8; ++ks) {
                #pragma unroll
                for (int nt = 0; nt < 4; ++nt) {
                    unsigned bf[2];
                    bf[0] = Ks[(nt*8 + g)*68 + ks*8 + t];
                    bf[1] = Ks[(nt*8 + g)*68 + ks*8 + t + 4];
                    mma8(s[nt], qf[ks], bf);
                }
            }

            // scale + causal mask + row max
            float mx0 = -CUDART_INF_F, mx1 = -CUDART_INF_F;
            #pragma unroll
            for (int nt = 0; nt < 4; ++nt) {
                int c0 = kt*32 + nt*8 + 2*t;
                s[nt][0] = (c0     <= r0) ? s[nt][0]*0.125f : -CUDART_INF_F;
                s[nt][1] = (c0 + 1 <= r0) ? s[nt][1]*0.125f : -CUDART_INF_F;
                s[nt][2] = (c0     <= r1) ? s[nt][2]*0.125f : -CUDART_INF_F;
                s[nt][3] = (c0 + 1 <= r1) ? s[nt][3]*0.125f : -CUDART_INF_F;
                mx0 = fmaxf(mx0, fmaxf(s[nt][0], s[nt][1]));
                mx1 = fmaxf(mx1, fmaxf(s[nt][2], s[nt][3]));
            }
            mx0 = fmaxf(mx0, __shfl_xor_sync(0xffffffffu, mx0, 1));
            mx0 = fmaxf(mx0, __shfl_xor_sync(0xffffffffu, mx0, 2));
            mx1 = fmaxf(mx1, __shfl_xor_sync(0xffffffffu, mx1, 1));
            mx1 = fmaxf(mx1, __shfl_xor_sync(0xffffffffu, mx1, 2));

            float mn0 = fmaxf(m0, mx0), mn1 = fmaxf(m1, mx1);
            float c0f = exp2f((m0 - mn0) * L2E);
            float c1f = exp2f((m1 - mn1) * L2E);
            m0 = mn0; m1 = mn1;

            float ps0 = 0.f, ps1 = 0.f;
            #pragma unroll
            for (int nt = 0; nt < 4; ++nt) {
                float p0 = exp2f((s[nt][0] - m0) * L2E);
                float p1 = exp2f((s[nt][1] - m0) * L2E);
                float p2 = exp2f((s[nt][2] - m1) * L2E);
                float p3 = exp2f((s[nt][3] - m1) * L2E);
                ps0 += p0 + p1;
                ps1 += p2 + p3;
                *(uint2*)(Pw + g*36 + nt*8 + 2*t)       = make_uint2(f2tf(p0), f2tf(p1));
                *(uint2*)(Pw + (g+8)*36 + nt*8 + 2*t)   = make_uint2(f2tf(p2), f2tf(p3));
            }
            ps0 += __shfl_xor_sync(0xffffffffu, ps0, 1);
            ps0 += __shfl_xor_sync(0xffffffffu, ps0, 2);
            ps1 += __shfl_xor_sync(0xffffffffu, ps1, 1);
            ps1 += __shfl_xor_sync(0xffffffffu, ps1, 2);
            l0 = l0*c0f + ps0;
            l1 = l1*c1f + ps1;

            #pragma unroll
            for (int n = 0; n < 8; ++n) {
                o[n][0] *= c0f; o[n][1] *= c0f;
                o[n][2] *= c1f; o[n][3] *= c1f;
            }
            __syncwarp();

            // O += P @ V  (k over 32 keys)
            #pragma unroll
            for (int ks = 0; ks < 4; ++ks) {
                unsigned af[4];
                af[0] = Pw[g*36 + ks*8 + t];
                af[1] = Pw[(g+8)*36 + ks*8 + t];
                af[2] = Pw[g*36 + ks*8 + t + 4];
                af[3] = Pw[(g+8)*36 + ks*8 + t + 4];
                #pragma unroll
                for (int n = 0; n < 8; ++n) {
                    unsigned bf[2];
                    bf[0] = Vs[(ks*8 + t)*72 + n*8 + g];
                    bf[1] = Vs[(ks*8 + t + 4)*72 + n*8 + g];
                    mma8(o[n], af, bf);
                }
            }
        }
        __syncthreads();
    }

    float i0 = 1.f / l0, i1 = 1.f / l1;
    #pragma unroll
    for (int n = 0; n < 8; ++n) {
        *(float2*)(Op + (size_t)r0*HD + n*8 + 2*t) =
            make_float2(o[n][0]*i0, o[n][1]*i0);
        *(float2*)(Op + (size_t)r1*HD + n*8 + 2*t) =
            make_float2(o[n][2]*i1, o[n][3]*i1);
    }
}

// ---------------------------------------------------------------------------
// Kernel 3: out = attn_out(gathered) @ w_proj via tf32 mma.sync.
// ---------------------------------------------------------------------------
__global__ __launch_bounds__(256) void proj_gemm(
    const float* __restrict__ W, float* __restrict__ out)
{
    __shared__ __align__(16) unsigned As[128*PK];
    __shared__ __align__(16) unsigned Bs[KC*PN];

    const int tid  = threadIdx.x;
    const int lane = tid & 31;
    const int w    = tid >> 5;
    const int wm   = w >> 2;
    const int wn   = w & 3;
    const int g    = lane >> 2;
    const int t    = lane & 3;
    const int bm   = blockIdx.y, bn = blockIdx.x;

    const int am  = tid >> 1;
    const int akq = (tid & 1) * 8;
    const int bkr = tid >> 4;
    const int bnq = (tid & 15) * 8;

    const int m_a = bm*128 + am;
    const int b_a = m_a >> 8, t_a = m_a & 255;
    const float* bptr = W + (size_t)bkr*NEMB + bn*128 + bnq;

    float acc[4][4][4];
    #pragma unroll
    for (int i = 0; i < 4; ++i)
        #pragma unroll
        for (int j = 0; j < 4; ++j)
            #pragma unroll
            for (int q = 0; q < 4; ++q) acc[i][j][q] = 0.f;

    unsigned ra[8], rb[8];
    {
        int kk = akq;
        int h = kk >> 6, d = kk & 63;
        const float* ap = g_o + (((size_t)(b_a*NHEAD + h))*SEQ + t_a)*HD + d;
        float4 x0 = *(const float4*)(ap);
        float4 x1 = *(const float4*)(ap + 4);
        ra[0]=f2tf(x0.x); ra[1]=f2tf(x0.y); ra[2]=f2tf(x0.z); ra[3]=f2tf(x0.w);
        ra[4]=f2tf(x1.x); ra[5]=f2tf(x1.y); ra[6]=f2tf(x1.z); ra[7]=f2tf(x1.w);
        float4 b0 = *(const float4*)(bptr);
        float4 b1 = *(const float4*)(bptr + 4);
        rb[0]=f2tf(b0.x); rb[1]=f2tf(b0.y); rb[2]=f2tf(b0.z); rb[3]=f2tf(b0.w);
        rb[4]=f2tf(b1.x); rb[5]=f2tf(b1.y); rb[6]=f2tf(b1.z); rb[7]=f2tf(b1.w);
    }

    for (int c = 0; c < NEMB/KC; ++c) {
        *(uint4*)(As + am*PK + akq)     = make_uint4(ra[0],ra[1],ra[2],ra[3]);
        *(uint4*)(As + am*PK + akq + 4) = make_uint4(ra[4],ra[5],ra[6],ra[7]);
        *(uint4*)(Bs + bkr*PN + bnq)     = make_uint4(rb[0],rb[1],rb[2],rb[3]);
        *(uint4*)(Bs + bkr*PN + bnq + 4) = make_uint4(rb[4],rb[5],rb[6],rb[7]);
        __syncthreads();

        if (c + 1 < NEMB/KC) {
            int kk = (c+1)*KC + akq;
            int h = kk >> 6, d = kk & 63;
            const float* ap = g_o + (((size_t)(b_a*NHEAD + h))*SEQ + t_a)*HD + d;
            float4 x0 = *(const float4*)(ap);
            float4 x1 = *(const float4*)(ap + 4);
            ra[0]=f2tf(x0.x); ra[1]=f2tf(x0.y); ra[2]=f2tf(x0.z); ra[3]=f2tf(x0.w);
            ra[4]=f2tf(x1.x); ra[5]=f2tf(x1.y); ra[6]=f2tf(x1.z); ra[7]=f2tf(x1.w);
            const float* bp = bptr + (size_t)(c+1)*KC*NEMB;
            float4 b0 = *(const float4*)(bp);
            float4 b1 = *(const float4*)(bp + 4);
            rb[0]=f2tf(b0.x); rb[1]=f2tf(b0.y); rb[2]=f2tf(b0.z); rb[3]=f2tf(b0.w);
            rb[4]=f2tf(b1.x); rb[5]=f2tf(b1.y); rb[6]=f2tf(b1.z); rb[7]=f2tf(b1.w);
        }

        #pragma unroll
        for (int ks = 0; ks < 2; ++ks) {
            unsigned af[4][4], bf[4][2];
            const int kk = ks*8 + t;
            #pragma unroll
            for (int mf = 0; mf < 4; ++mf) {
                int r = wm*64 + mf*16 + g;
                af[mf][0] = As[r*PK + kk];
                af[mf][1] = As[(r+8)*PK + kk];
                af[mf][2] = As[r*PK + kk + 4];
                af[mf][3] = As[(r+8)*PK + kk + 4];
            }
            #pragma unroll
            for (int nf = 0; nf < 4; ++nf) {
                int n = wn*32 + nf*8 + g;
                bf[nf][0] = Bs[kk*PN + n];
                bf[nf][1] = Bs[(kk+4)*PN + n];
            }
            #pragma unroll
            for (int mf = 0; mf < 4; ++mf)
                #pragma unroll
                for (int nf = 0; nf < 4; ++nf)
                    mma8(acc[mf][nf], af[mf], bf[nf]);
        }
        __syncthreads();
    }

    #pragma unroll
    for (int mf = 0; mf < 4; ++mf) {
        int r0 = bm*128 + wm*64 + mf*16 + g;
        #pragma unroll
        for (int half = 0; half < 2; ++half) {
            int row = r0 + 8*half;
            #pragma unroll
            for (int nf = 0; nf < 4; ++nf) {
                int nn = bn*128 + wn*32 + nf*8 + 2*t;
                *(float2*)(out + (size_t)row*NEMB + nn) =
                    make_float2(acc[mf][nf][2*half], acc[mf][nf][2*half+1]);
            }
        }
    }
}

// ---------------------------------------------------------------------------
extern "C" void kernel_launch(void* const* d_in, const int* in_sizes, int n_in,
                              void* d_out, int out_size)
{
    const float* x      = (const float*)d_in[0];   // [64,256,384]
    const float* w_attn = (const float*)d_in[1];   // [384,1152]
    const float* w_proj = (const float*)d_in[2];   // [384,384]
    float* out = (float*)d_out;                    // [64,256,384]

    dim3 g1(N_QKV/128, MTOT/128);   // (9, 128)
    qkv_gemm_rope<<<g1, 256>>>(x, w_attn);

    dim3 g2(BH, 2);                 // (384, 2) q-row blocks of 128
    attn_mma<<<g2, 256>>>();

    dim3 g3(NEMB/128, MTOT/128);    // (3, 128)
    proj_gemm<<<g3, 256>>>(w_proj, out);
}

// round 4
// speedup vs baseline: 3.2974x; 1.1932x over previous
#include <cuda_runtime.h>
#include <math.h>
#include <math_constants.h>

// Problem constants
#define BATCH   64
#define SEQ     256
#define NEMB    384
#define NHEAD   6
#define HD      64
#define BH      (BATCH*NHEAD)      // 384
#define MTOT    (BATCH*SEQ)        // 16384
#define N_QKV   (3*NEMB)           // 1152

#define PA  36          // A smem pitch (32 + 4)
#define PB  136         // B smem pitch (128 + 8)
#define NCHUNK (NEMB/32)            // 12

#define L2E 1.4426950408889634f

// Scratch
__device__ float g_q[BH*SEQ*HD];
__device__ float g_k[BH*SEQ*HD];
__device__ float g_v[BH*SEQ*HD];
__device__ float g_o[BH*SEQ*HD];
__device__ float g_xt[MTOT*NEMB];       // tf32-rounded x
__device__ float g_wat[NEMB*N_QKV];     // tf32-rounded w_attn
__device__ float g_wpt[NEMB*NEMB];      // tf32-rounded w_proj

__device__ __forceinline__ unsigned f2tf(float f) {
    unsigned u;
    asm("cvt.rna.tf32.f32 %0, %1;" : "=r"(u) : "f"(f));
    return u;
}

__device__ __forceinline__ void mma8(float* c, const unsigned* a, const unsigned* b) {
    asm volatile(
        "mma.sync.aligned.m16n8k8.row.col.f32.tf32.tf32.f32 "
        "{%0,%1,%2,%3}, {%4,%5,%6,%7}, {%8,%9}, {%0,%1,%2,%3};"
        : "+f"(c[0]), "+f"(c[1]), "+f"(c[2]), "+f"(c[3])
        : "r"(a[0]), "r"(a[1]), "r"(a[2]), "r"(a[3]),
          "r"(b[0]), "r"(b[1]));
}

__device__ __forceinline__ void cp16(unsigned* dst_smem, const void* src) {
    unsigned d = (unsigned)__cvta_generic_to_shared(dst_smem);
    asm volatile("cp.async.cg.shared.global [%0], [%1], 16;\n" :: "r"(d), "l"(src));
}
__device__ __forceinline__ void cp_commit() {
    asm volatile("cp.async.commit_group;\n");
}
template <int N> __device__ __forceinline__ void cp_wait() {
    asm volatile("cp.async.wait_group %0;\n" :: "n"(N));
}

// ---------------------------------------------------------------------------
// Kernel 0: tf32-round x, w_attn, w_proj into scratch (vectorized).
// ---------------------------------------------------------------------------
__global__ __launch_bounds__(256) void conv_tf32(
    const float* __restrict__ x, const float* __restrict__ wa,
    const float* __restrict__ wp)
{
    const int i = blockIdx.x*blockDim.x + threadIdx.x;   // float4 index
    const int NX4 = MTOT*NEMB/4, NA4 = NEMB*N_QKV/4, NP4 = NEMB*NEMB/4;
    if (i < NX4) {
        float4 v = ((const float4*)x)[i];
        ((uint4*)g_xt)[i] = make_uint4(f2tf(v.x),f2tf(v.y),f2tf(v.z),f2tf(v.w));
    }
    if (i < NA4) {
        float4 v = ((const float4*)wa)[i];
        ((uint4*)g_wat)[i] = make_uint4(f2tf(v.x),f2tf(v.y),f2tf(v.z),f2tf(v.w));
    }
    if (i < NP4) {
        float4 v = ((const float4*)wp)[i];
        ((uint4*)g_wpt)[i] = make_uint4(f2tf(v.x),f2tf(v.y),f2tf(v.z),f2tf(v.w));
    }
}

// ---------------------------------------------------------------------------
// Kernel 1: qkv = x @ w_attn (tf32 mma, cp.async double buffer, kc=32);
// epilogue RoPE + tf32-rounded scatter to g_q/g_k/g_v.
// Dynamic smem: As[2][128*PA] + Bs[2][32*PB] = 71680 B.
// ---------------------------------------------------------------------------
__global__ __launch_bounds__(256) void qkv_gemm_rope()
{
    extern __shared__ unsigned sm[];
    unsigned* Asb[2] = { sm,            sm + 128*PA };
    unsigned* Bsb[2] = { sm + 2*128*PA, sm + 2*128*PA + 32*PB };

    const int tid  = threadIdx.x;
    const int lane = tid & 31;
    const int w    = tid >> 5;
    const int wm   = w >> 2;
    const int wn   = w & 3;
    const int g    = lane >> 2;
    const int t    = lane & 3;
    const int bm   = blockIdx.y, bn = blockIdx.x;

    float acc[4][4][4];
    #pragma unroll
    for (int i = 0; i < 4; ++i)
        #pragma unroll
        for (int j = 0; j < 4; ++j)
            #pragma unroll
            for (int q = 0; q < 4; ++q) acc[i][j][q] = 0.f;

    // chunk loader: stage s <- k-chunk c (32 k's)
    auto load_chunk = [&](int c, int s) {
        #pragma unroll
        for (int u = 0; u < 4; ++u) {
            int id  = tid + 256*u;                 // 0..1023
            int row = id >> 3, off = (id & 7) * 4; // A: 128 rows x 8 chunks
            cp16(Asb[s] + row*PA + off,
                 g_xt + (size_t)(bm*128 + row)*NEMB + c*32 + off);
            int br = id >> 5, bo = (id & 31) * 4;  // B: 32 rows x 32 chunks
            cp16(Bsb[s] + br*PB + bo,
                 g_wat + (size_t)(c*32 + br)*N_QKV + bn*128 + bo);
        }
        cp_commit();
    };

    load_chunk(0, 0);
    for (int c = 0; c < NCHUNK; ++c) {
        const int s = c & 1;
        if (c + 1 < NCHUNK) { load_chunk(c+1, s^1); cp_wait<1>(); }
        else                { cp_wait<0>(); }
        __syncthreads();

        const unsigned* A = Asb[s];
        const unsigned* B = Bsb[s];
        #pragma unroll
        for (int ks = 0; ks < 4; ++ks) {
            const int kk = ks*8 + t;
            unsigned af[4][4], bf[4][2];
            #pragma unroll
            for (int mf = 0; mf < 4; ++mf) {
                int r = wm*64 + mf*16 + g;
                af[mf][0] = A[r*PA + kk];
                af[mf][1] = A[(r+8)*PA + kk];
                af[mf][2] = A[r*PA + kk + 4];
                af[mf][3] = A[(r+8)*PA + kk + 4];
            }
            #pragma unroll
            for (int nf = 0; nf < 4; ++nf) {
                int n = wn*32 + nf*8 + g;
                bf[nf][0] = B[kk*PB + n];
                bf[nf][1] = B[(kk+4)*PB + n];
            }
            #pragma unroll
            for (int mf = 0; mf < 4; ++mf)
                #pragma unroll
                for (int nf = 0; nf < 4; ++nf)
                    mma8(acc[mf][nf], af[mf], bf[nf]);
        }
        __syncthreads();
    }

    // Epilogue: RoPE + scatter, tf32-rounded outputs.
    const int section = bn / 3;  // 0=q 1=k 2=v
    float* dst = (section == 0) ? g_q : (section == 1) ? g_k : g_v;
    const int ncol0 = (bn % 3) * 128;

    float invf[4];
    #pragma unroll
    for (int nf = 0; nf < 4; ++nf) {
        int d = (ncol0 + wn*32 + nf*8 + 2*t) & 63;
        invf[nf] = exp2f((float)d * (-13.287712379549449f/64.f));
    }

    #pragma unroll
    for (int mf = 0; mf < 4; ++mf) {
        int r0 = bm*128 + wm*64 + mf*16 + g;
        #pragma unroll
        for (int half = 0; half < 2; ++half) {
            int row = r0 + 8*half;
            int b = row >> 8, tt = row & 255;
            #pragma unroll
            for (int nf = 0; nf < 4; ++nf) {
                int nn = ncol0 + wn*32 + nf*8 + 2*t;
                int h = nn >> 6, d = nn & 63;
                size_t base = (((size_t)(b*NHEAD + h))*SEQ + tt)*HD + d;
                float e = acc[mf][nf][2*half];
                float o = acc[mf][nf][2*half + 1];
                float v0, v1;
                if (section == 2) { v0 = e; v1 = o; }
                else {
                    float theta = (float)tt * invf[nf];
                    float sn, cs;
                    sincosf(theta, &sn, &cs);
                    v0 = e*cs - o*sn; v1 = o*cs + e*sn;
                }
                *(uint2*)(dst + base) = make_uint2(f2tf(v0), f2tf(v1));
            }
        }
    }
}

// ---------------------------------------------------------------------------
// Kernel 2: tensor-core causal flash attention (tf32 mma).
// q/k/v already tf32-rounded -> raw-bit loads, no conversion in loop.
// ---------------------------------------------------------------------------
__global__ __launch_bounds__(256) void attn_mma()
{
    __shared__ __align__(16) unsigned Ks[32*68];
    __shared__ __align__(16) unsigned Vs[32*72];
    __shared__ __align__(16) unsigned Ps[8*16*36];

    const int tid  = threadIdx.x;
    const int lane = tid & 31;
    const int w    = tid >> 5;
    const int g    = lane >> 2;
    const int t    = lane & 3;
    const int bh   = blockIdx.x;
    const int qb   = blockIdx.y;

    const unsigned* Qp = (const unsigned*)g_q + (size_t)bh*SEQ*HD;
    const unsigned* Kp = (const unsigned*)g_k + (size_t)bh*SEQ*HD;
    const unsigned* Vp = (const unsigned*)g_v + (size_t)bh*SEQ*HD;
    float*          Op = g_o + (size_t)bh*SEQ*HD;

    const int qrow0 = qb*128 + w*16;
    const int r0 = qrow0 + g, r1 = qrow0 + g + 8;

    unsigned qf[8][4];
    #pragma unroll
    for (int ks = 0; ks < 8; ++ks) {
        qf[ks][0] = Qp[(size_t)r0*HD + ks*8 + t];
        qf[ks][1] = Qp[(size_t)r1*HD + ks*8 + t];
        qf[ks][2] = Qp[(size_t)r0*HD + ks*8 + t + 4];
        qf[ks][3] = Qp[(size_t)r1*HD + ks*8 + t + 4];
    }

    float o[8][4];
    #pragma unroll
    for (int n = 0; n < 8; ++n)
        #pragma unroll
        for (int q = 0; q < 4; ++q) o[n][q] = 0.f;
    float m0 = -CUDART_INF_F, m1 = -CUDART_INF_F;
    float l0 = 0.f, l1 = 0.f;

    const int ntiles = qb*4 + 4;
    unsigned* Pw = Ps + w*16*36;

    for (int kt = 0; kt < ntiles; ++kt) {
        #pragma unroll
        for (int u = 0; u < 2; ++u) {
            int i = tid + 256*u;
            int row = i >> 4, c4 = (i & 15) * 4;
            *(uint4*)(Ks + row*68 + c4) =
                *(const uint4*)(Kp + (size_t)(kt*32 + row)*HD + c4);
            *(uint4*)(Vs + row*72 + c4) =
                *(const uint4*)(Vp + (size_t)(kt*32 + row)*HD + c4);
        }
        __syncthreads();

        if (kt*32 <= qrow0 + 15) {
            float s[4][4];
            #pragma unroll
            for (int nt = 0; nt < 4; ++nt)
                #pragma unroll
                for (int q = 0; q < 4; ++q) s[nt][q] = 0.f;
            #pragma unroll
            for (int ks = 0; ks < 8; ++ks) {
                #pragma unroll
                for (int nt = 0; nt < 4; ++nt) {
                    unsigned bf[2];
                    bf[0] = Ks[(nt*8 + g)*68 + ks*8 + t];
                    bf[1] = Ks[(nt*8 + g)*68 + ks*8 + t + 4];
                    mma8(s[nt], qf[ks], bf);
                }
            }

            float mx0 = -CUDART_INF_F, mx1 = -CUDART_INF_F;
            #pragma unroll
            for (int nt = 0; nt < 4; ++nt) {
                int c0 = kt*32 + nt*8 + 2*t;
                s[nt][0] = (c0     <= r0) ? s[nt][0]*0.125f : -CUDART_INF_F;
                s[nt][1] = (c0 + 1 <= r0) ? s[nt][1]*0.125f : -CUDART_INF_F;
                s[nt][2] = (c0     <= r1) ? s[nt][2]*0.125f : -CUDART_INF_F;
                s[nt][3] = (c0 + 1 <= r1) ? s[nt][3]*0.125f : -CUDART_INF_F;
                mx0 = fmaxf(mx0, fmaxf(s[nt][0], s[nt][1]));
                mx1 = fmaxf(mx1, fmaxf(s[nt][2], s[nt][3]));
            }
            mx0 = fmaxf(mx0, __shfl_xor_sync(0xffffffffu, mx0, 1));
            mx0 = fmaxf(mx0, __shfl_xor_sync(0xffffffffu, mx0, 2));
            mx1 = fmaxf(mx1, __shfl_xor_sync(0xffffffffu, mx1, 1));
            mx1 = fmaxf(mx1, __shfl_xor_sync(0xffffffffu, mx1, 2));

            float mn0 = fmaxf(m0, mx0), mn1 = fmaxf(m1, mx1);
            float c0f = exp2f((m0 - mn0) * L2E);
            float c1f = exp2f((m1 - mn1) * L2E);
            m0 = mn0; m1 = mn1;

            float ps0 = 0.f, ps1 = 0.f;
            #pragma unroll
            for (int nt = 0; nt < 4; ++nt) {
                float p0 = exp2f((s[nt][0] - m0) * L2E);
                float p1 = exp2f((s[nt][1] - m0) * L2E);
                float p2 = exp2f((s[nt][2] - m1) * L2E);
                float p3 = exp2f((s[nt][3] - m1) * L2E);
                ps0 += p0 + p1;
                ps1 += p2 + p3;
                *(uint2*)(Pw + g*36 + nt*8 + 2*t)     = make_uint2(f2tf(p0), f2tf(p1));
                *(uint2*)(Pw + (g+8)*36 + nt*8 + 2*t) = make_uint2(f2tf(p2), f2tf(p3));
            }
            ps0 += __shfl_xor_sync(0xffffffffu, ps0, 1);
            ps0 += __shfl_xor_sync(0xffffffffu, ps0, 2);
            ps1 += __shfl_xor_sync(0xffffffffu, ps1, 1);
            ps1 += __shfl_xor_sync(0xffffffffu, ps1, 2);
            l0 = l0*c0f + ps0;
            l1 = l1*c1f + ps1;

            #pragma unroll
            for (int n = 0; n < 8; ++n) {
                o[n][0] *= c0f; o[n][1] *= c0f;
                o[n][2] *= c1f; o[n][3] *= c1f;
            }
            __syncwarp();

            #pragma unroll
            for (int ks = 0; ks < 4; ++ks) {
                unsigned af[4];
                af[0] = Pw[g*36 + ks*8 + t];
                af[1] = Pw[(g+8)*36 + ks*8 + t];
                af[2] = Pw[g*36 + ks*8 + t + 4];
                af[3] = Pw[(g+8)*36 + ks*8 + t + 4];
                #pragma unroll
                for (int n = 0; n < 8; ++n) {
                    unsigned bf[2];
                    bf[0] = Vs[(ks*8 + t)*72 + n*8 + g];
                    bf[1] = Vs[(ks*8 + t + 4)*72 + n*8 + g];
                    mma8(o[n], af, bf);
                }
            }
        }
        __syncthreads();
    }

    // write tf32-rounded so proj needs no conversion
    float i0 = 1.f / l0, i1 = 1.f / l1;
    #pragma unroll
    for (int n = 0; n < 8; ++n) {
        *(uint2*)(Op + (size_t)r0*HD + n*8 + 2*t) =
            make_uint2(f2tf(o[n][0]*i0), f2tf(o[n][1]*i0));
        *(uint2*)(Op + (size_t)r1*HD + n*8 + 2*t) =
            make_uint2(f2tf(o[n][2]*i1), f2tf(o[n][3]*i1));
    }
}

// ---------------------------------------------------------------------------
// Kernel 3: out = attn_out(gathered) @ w_proj (cp.async double buffer).
// ---------------------------------------------------------------------------
__global__ __launch_bounds__(256) void proj_gemm(float* __restrict__ out)
{
    extern __shared__ unsigned sm[];
    unsigned* Asb[2] = { sm,            sm + 128*PA };
    unsigned* Bsb[2] = { sm + 2*128*PA, sm + 2*128*PA + 32*PB };

    const int tid  = threadIdx.x;
    const int lane = tid & 31;
    const int w    = tid >> 5;
    const int wm   = w >> 2;
    const int wn   = w & 3;
    const int g    = lane >> 2;
    const int t    = lane & 3;
    const int bm   = blockIdx.y, bn = blockIdx.x;

    float acc[4][4][4];
    #pragma unroll
    for (int i = 0; i < 4; ++i)
        #pragma unroll
        for (int j = 0; j < 4; ++j)
            #pragma unroll
            for (int q = 0; q < 4; ++q) acc[i][j][q] = 0.f;

    auto load_chunk = [&](int c, int s) {
        #pragma unroll
        for (int u = 0; u < 4; ++u) {
            int id  = tid + 256*u;
            int row = id >> 3, off = (id & 7) * 4;
            int kk = c*32 + off;
            int h = kk >> 6, d = kk & 63;
            int m = bm*128 + row;
            int b = m >> 8, tt = m & 255;
            cp16(Asb[s] + row*PA + off,
                 g_o + (((size_t)(b*NHEAD + h))*SEQ + tt)*HD + d);
            int br = id >> 5, bo = (id & 31) * 4;
            cp16(Bsb[s] + br*PB + bo,
                 g_wpt + (size_t)(c*32 + br)*NEMB + bn*128 + bo);
        }
        cp_commit();
    };

    load_chunk(0, 0);
    for (int c = 0; c < NCHUNK; ++c) {
        const int s = c & 1;
        if (c + 1 < NCHUNK) { load_chunk(c+1, s^1); cp_wait<1>(); }
        else                { cp_wait<0>(); }
        __syncthreads();

        const unsigned* A = Asb[s];
        const unsigned* B = Bsb[s];
        #pragma unroll
        for (int ks = 0; ks < 4; ++ks) {
            const int kk = ks*8 + t;
            unsigned af[4][4], bf[4][2];
            #pragma unroll
            for (int mf = 0; mf < 4; ++mf) {
                int r = wm*64 + mf*16 + g;
                af[mf][0] = A[r*PA + kk];
                af[mf][1] = A[(r+8)*PA + kk];
                af[mf][2] = A[r*PA + kk + 4];
                af[mf][3] = A[(r+8)*PA + kk + 4];
            }
            #pragma unroll
            for (int nf = 0; nf < 4; ++nf) {
                int n = wn*32 + nf*8 + g;
                bf[nf][0] = B[kk*PB + n];
                bf[nf][1] = B[(kk+4)*PB + n];
            }
            #pragma unroll
            for (int mf = 0; mf < 4; ++mf)
                #pragma unroll
                for (int nf = 0; nf < 4; ++nf)
                    mma8(acc[mf][nf], af[mf], bf[nf]);
        }
        __syncthreads();
    }

    #pragma unroll
    for (int mf = 0; mf < 4; ++mf) {
        int r0 = bm*128 + wm*64 + mf*16 + g;
        #pragma unroll
        for (int half = 0; half < 2; ++half) {
            int row = r0 + 8*half;
            #pragma unroll
            for (int nf = 0; nf < 4; ++nf) {
                int nn = bn*128 + wn*32 + nf*8 + 2*t;
                *(float2*)(out + (size_t)row*NEMB + nn) =
                    make_float2(acc[mf][nf][2*half], acc[mf][nf][2*half+1]);
            }
        }
    }
}

// ---------------------------------------------------------------------------
extern "C" void kernel_launch(void* const* d_in, const int* in_sizes, int n_in,
                              void* d_out, int out_size)
{
    const float* x      = (const float*)d_in[0];
    const float* w_attn = (const float*)d_in[1];
    const float* w_proj = (const float*)d_in[2];
    float* out = (float*)d_out;

    const int SMEM_GEMM = (2*128*PA + 2*32*PB) * 4;   // 71680 B
    cudaFuncSetAttribute(qkv_gemm_rope,
        cudaFuncAttributeMaxDynamicSharedMemorySize, SMEM_GEMM);
    cudaFuncSetAttribute(proj_gemm,
        cudaFuncAttributeMaxDynamicSharedMemorySize, SMEM_GEMM);

    // convert pass: cover max(NX4, ...) float4 elements
    const int NX4 = MTOT*NEMB/4;
    conv_tf32<<<(NX4 + 255)/256, 256>>>(x, w_attn, w_proj);

    dim3 g1(N_QKV/128, MTOT/128);   // (9, 128)
    qkv_gemm_rope<<<g1, 256, SMEM_GEMM>>>();

    dim3 g2(BH, 2);
    attn_mma<<<g2, 256>>>();

    dim3 g3(NEMB/128, MTOT/128);    // (3, 128)
    proj_gemm<<<g3, 256, SMEM_GEMM>>>(out);
}

// round 5
// speedup vs baseline: 3.3938x; 1.0292x over previous
#include <cuda_runtime.h>
#include <math.h>
#include <math_constants.h>

// Problem constants
#define BATCH   64
#define SEQ     256
#define NEMB    384
#define NHEAD   6
#define HD      64
#define BH      (BATCH*NHEAD)      // 384
#define MTOT    (BATCH*SEQ)        // 16384
#define N_QKV   (3*NEMB)           // 1152

#define PA  36          // A smem pitch (32 + 4)
#define PB  136         // B smem pitch (128 + 8)
#define NCHUNK (NEMB/32)            // 12

#define PKV 68          // attn K pitch
#define PVV 72          // attn V pitch

#define L2E 1.4426950408889634f

// Scratch
__device__ float g_q[BH*SEQ*HD];
__device__ float g_k[BH*SEQ*HD];
__device__ float g_v[BH*SEQ*HD];
__device__ float g_o[BH*SEQ*HD];
__device__ float g_xt[MTOT*NEMB];       // tf32-rounded x
__device__ float g_wat[NEMB*N_QKV];     // tf32-rounded w_attn
__device__ float g_wpt[NEMB*NEMB];      // tf32-rounded w_proj

__device__ __forceinline__ unsigned f2tf(float f) {
    unsigned u;
    asm("cvt.rna.tf32.f32 %0, %1;" : "=r"(u) : "f"(f));
    return u;
}

__device__ __forceinline__ void mma8(float* c, const unsigned* a, const unsigned* b) {
    asm volatile(
        "mma.sync.aligned.m16n8k8.row.col.f32.tf32.tf32.f32 "
        "{%0,%1,%2,%3}, {%4,%5,%6,%7}, {%8,%9}, {%0,%1,%2,%3};"
        : "+f"(c[0]), "+f"(c[1]), "+f"(c[2]), "+f"(c[3])
        : "r"(a[0]), "r"(a[1]), "r"(a[2]), "r"(a[3]),
          "r"(b[0]), "r"(b[1]));
}

__device__ __forceinline__ void cp16(unsigned* dst_smem, const void* src) {
    unsigned d = (unsigned)__cvta_generic_to_shared(dst_smem);
    asm volatile("cp.async.cg.shared.global [%0], [%1], 16;\n" :: "r"(d), "l"(src));
}
__device__ __forceinline__ void cp_commit() {
    asm volatile("cp.async.commit_group;\n");
}
template <int N> __device__ __forceinline__ void cp_wait() {
    asm volatile("cp.async.wait_group %0;\n" :: "n"(N));
}

// ---------------------------------------------------------------------------
// Kernel 0: tf32-round x, w_attn, w_proj into scratch (vectorized).
// ---------------------------------------------------------------------------
__global__ __launch_bounds__(256) void conv_tf32(
    const float* __restrict__ x, const float* __restrict__ wa,
    const float* __restrict__ wp)
{
    const int i = blockIdx.x*blockDim.x + threadIdx.x;
    const int NX4 = MTOT*NEMB/4, NA4 = NEMB*N_QKV/4, NP4 = NEMB*NEMB/4;
    if (i < NX4) {
        float4 v = ((const float4*)x)[i];
        ((uint4*)g_xt)[i] = make_uint4(f2tf(v.x),f2tf(v.y),f2tf(v.z),f2tf(v.w));
    }
    if (i < NA4) {
        float4 v = ((const float4*)wa)[i];
        ((uint4*)g_wat)[i] = make_uint4(f2tf(v.x),f2tf(v.y),f2tf(v.z),f2tf(v.w));
    }
    if (i < NP4) {
        float4 v = ((const float4*)wp)[i];
        ((uint4*)g_wpt)[i] = make_uint4(f2tf(v.x),f2tf(v.y),f2tf(v.z),f2tf(v.w));
    }
}

// ---------------------------------------------------------------------------
// Kernel 1: qkv = x @ w_attn (tf32 mma, cp.async double buffer, kc=32);
// epilogue RoPE + tf32-rounded scatter. __launch_bounds__(256,2) -> <=128 regs.
// ---------------------------------------------------------------------------
__global__ __launch_bounds__(256, 2) void qkv_gemm_rope()
{
    extern __shared__ unsigned sm[];
    unsigned* Asb[2] = { sm,            sm + 128*PA };
    unsigned* Bsb[2] = { sm + 2*128*PA, sm + 2*128*PA + 32*PB };

    const int tid  = threadIdx.x;
    const int lane = tid & 31;
    const int w    = tid >> 5;
    const int wm   = w >> 2;
    const int wn   = w & 3;
    const int g    = lane >> 2;
    const int t    = lane & 3;
    const int bm   = blockIdx.y, bn = blockIdx.x;

    float acc[4][4][4];
    #pragma unroll
    for (int i = 0; i < 4; ++i)
        #pragma unroll
        for (int j = 0; j < 4; ++j)
            #pragma unroll
            for (int q = 0; q < 4; ++q) acc[i][j][q] = 0.f;

    auto load_chunk = [&](int c, int s) {
        #pragma unroll
        for (int u = 0; u < 4; ++u) {
            int id  = tid + 256*u;
            int row = id >> 3, off = (id & 7) * 4;
            cp16(Asb[s] + row*PA + off,
                 g_xt + (size_t)(bm*128 + row)*NEMB + c*32 + off);
            int br = id >> 5, bo = (id & 31) * 4;
            cp16(Bsb[s] + br*PB + bo,
                 g_wat + (size_t)(c*32 + br)*N_QKV + bn*128 + bo);
        }
        cp_commit();
    };

    load_chunk(0, 0);
    for (int c = 0; c < NCHUNK; ++c) {
        const int s = c & 1;
        if (c + 1 < NCHUNK) { load_chunk(c+1, s^1); cp_wait<1>(); }
        else                { cp_wait<0>(); }
        __syncthreads();

        const unsigned* A = Asb[s];
        const unsigned* B = Bsb[s];
        #pragma unroll
        for (int ks = 0; ks < 4; ++ks) {
            const int kk = ks*8 + t;
            unsigned af[4][4], bf[4][2];
            #pragma unroll
            for (int mf = 0; mf < 4; ++mf) {
                int r = wm*64 + mf*16 + g;
                af[mf][0] = A[r*PA + kk];
                af[mf][1] = A[(r+8)*PA + kk];
                af[mf][2] = A[r*PA + kk + 4];
                af[mf][3] = A[(r+8)*PA + kk + 4];
            }
            #pragma unroll
            for (int nf = 0; nf < 4; ++nf) {
                int n = wn*32 + nf*8 + g;
                bf[nf][0] = B[kk*PB + n];
                bf[nf][1] = B[(kk+4)*PB + n];
            }
            #pragma unroll
            for (int mf = 0; mf < 4; ++mf)
                #pragma unroll
                for (int nf = 0; nf < 4; ++nf)
                    mma8(acc[mf][nf], af[mf], bf[nf]);
        }
        __syncthreads();
    }

    const int section = bn / 3;  // 0=q 1=k 2=v
    float* dst = (section == 0) ? g_q : (section == 1) ? g_k : g_v;
    const int ncol0 = (bn % 3) * 128;

    float invf[4];
    #pragma unroll
    for (int nf = 0; nf < 4; ++nf) {
        int d = (ncol0 + wn*32 + nf*8 + 2*t) & 63;
        invf[nf] = exp2f((float)d * (-13.287712379549449f/64.f));
    }

    #pragma unroll
    for (int mf = 0; mf < 4; ++mf) {
        int r0 = bm*128 + wm*64 + mf*16 + g;
        #pragma unroll
        for (int half = 0; half < 2; ++half) {
            int row = r0 + 8*half;
            int b = row >> 8, tt = row & 255;
            #pragma unroll
            for (int nf = 0; nf < 4; ++nf) {
                int nn = ncol0 + wn*32 + nf*8 + 2*t;
                int h = nn >> 6, d = nn & 63;
                size_t base = (((size_t)(b*NHEAD + h))*SEQ + tt)*HD + d;
                float e = acc[mf][nf][2*half];
                float o = acc[mf][nf][2*half + 1];
                float v0, v1;
                if (section == 2) { v0 = e; v1 = o; }
                else {
                    float theta = (float)tt * invf[nf];
                    float sn, cs;
                    sincosf(theta, &sn, &cs);
                    v0 = e*cs - o*sn; v1 = o*cs + e*sn;
                }
                *(uint2*)(dst + base) = make_uint2(f2tf(v0), f2tf(v1));
            }
        }
    }
}

// ---------------------------------------------------------------------------
// Kernel 2: tensor-core causal flash attention (tf32 mma), cp.async
// double-buffered K/V tiles. Dynamic smem: 2*(32*68 + 32*72) + 8*16*36 words.
// ---------------------------------------------------------------------------
#define ATTN_SMEM_WORDS (2*32*PKV + 2*32*PVV + 8*16*36)

__global__ __launch_bounds__(256) void attn_mma()
{
    extern __shared__ unsigned asm_[];
    unsigned* Ksb[2] = { asm_,            asm_ + 32*PKV };
    unsigned* Vsb[2] = { asm_ + 2*32*PKV, asm_ + 2*32*PKV + 32*PVV };
    unsigned* Ps     = asm_ + 2*32*PKV + 2*32*PVV;

    const int tid  = threadIdx.x;
    const int lane = tid & 31;
    const int w    = tid >> 5;
    const int g    = lane >> 2;
    const int t    = lane & 3;
    const int bh   = blockIdx.x;
    const int qb   = blockIdx.y;

    const unsigned* Qp = (const unsigned*)g_q + (size_t)bh*SEQ*HD;
    const unsigned* Kp = (const unsigned*)g_k + (size_t)bh*SEQ*HD;
    const unsigned* Vp = (const unsigned*)g_v + (size_t)bh*SEQ*HD;
    float*          Op = g_o + (size_t)bh*SEQ*HD;

    const int qrow0 = qb*128 + w*16;
    const int r0 = qrow0 + g, r1 = qrow0 + g + 8;

    unsigned qf[8][4];
    #pragma unroll
    for (int ks = 0; ks < 8; ++ks) {
        qf[ks][0] = Qp[(size_t)r0*HD + ks*8 + t];
        qf[ks][1] = Qp[(size_t)r1*HD + ks*8 + t];
        qf[ks][2] = Qp[(size_t)r0*HD + ks*8 + t + 4];
        qf[ks][3] = Qp[(size_t)r1*HD + ks*8 + t + 4];
    }

    float o[8][4];
    #pragma unroll
    for (int n = 0; n < 8; ++n)
        #pragma unroll
        for (int q = 0; q < 4; ++q) o[n][q] = 0.f;
    float m0 = -CUDART_INF_F, m1 = -CUDART_INF_F;
    float l0 = 0.f, l1 = 0.f;

    const int ntiles = qb*4 + 4;
    unsigned* Pw = Ps + w*16*36;

    auto load_tile = [&](int kt, int s) {
        #pragma unroll
        for (int u = 0; u < 2; ++u) {
            int i = tid + 256*u;               // 0..511 float4 slots
            int row = i >> 4, c4 = (i & 15) * 4;
            cp16(Ksb[s] + row*PKV + c4, Kp + (size_t)(kt*32 + row)*HD + c4);
            cp16(Vsb[s] + row*PVV + c4, Vp + (size_t)(kt*32 + row)*HD + c4);
        }
        cp_commit();
    };

    load_tile(0, 0);
    for (int kt = 0; kt < ntiles; ++kt) {
        const int s = kt & 1;
        if (kt + 1 < ntiles) { load_tile(kt+1, s^1); cp_wait<1>(); }
        else                 { cp_wait<0>(); }
        __syncthreads();

        if (kt*32 <= qrow0 + 15) {
            const unsigned* Ks = Ksb[s];
            const unsigned* Vs = Vsb[s];

            float sc[4][4];
            #pragma unroll
            for (int nt = 0; nt < 4; ++nt)
                #pragma unroll
                for (int q = 0; q < 4; ++q) sc[nt][q] = 0.f;
            #pragma unroll
            for (int ks = 0; ks < 8; ++ks) {
                #pragma unroll
                for (int nt = 0; nt < 4; ++nt) {
                    unsigned bf[2];
                    bf[0] = Ks[(nt*8 + g)*PKV + ks*8 + t];
                    bf[1] = Ks[(nt*8 + g)*PKV + ks*8 + t + 4];
                    mma8(sc[nt], qf[ks], bf);
                }
            }

            float mx0 = -CUDART_INF_F, mx1 = -CUDART_INF_F;
            #pragma unroll
            for (int nt = 0; nt < 4; ++nt) {
                int c0 = kt*32 + nt*8 + 2*t;
                sc[nt][0] = (c0     <= r0) ? sc[nt][0]*0.125f : -CUDART_INF_F;
                sc[nt][1] = (c0 + 1 <= r0) ? sc[nt][1]*0.125f : -CUDART_INF_F;
                sc[nt][2] = (c0     <= r1) ? sc[nt][2]*0.125f : -CUDART_INF_F;
                sc[nt][3] = (c0 + 1 <= r1) ? sc[nt][3]*0.125f : -CUDART_INF_F;
                mx0 = fmaxf(mx0, fmaxf(sc[nt][0], sc[nt][1]));
                mx1 = fmaxf(mx1, fmaxf(sc[nt][2], sc[nt][3]));
            }
            mx0 = fmaxf(mx0, __shfl_xor_sync(0xffffffffu, mx0, 1));
            mx0 = fmaxf(mx0, __shfl_xor_sync(0xffffffffu, mx0, 2));
            mx1 = fmaxf(mx1, __shfl_xor_sync(0xffffffffu, mx1, 1));
            mx1 = fmaxf(mx1, __shfl_xor_sync(0xffffffffu, mx1, 2));

            float mn0 = fmaxf(m0, mx0), mn1 = fmaxf(m1, mx1);
            float c0f = exp2f((m0 - mn0) * L2E);
            float c1f = exp2f((m1 - mn1) * L2E);
            m0 = mn0; m1 = mn1;

            float ps0 = 0.f, ps1 = 0.f;
            #pragma unroll
            for (int nt = 0; nt < 4; ++nt) {
                float p0 = exp2f((sc[nt][0] - m0) * L2E);
                float p1 = exp2f((sc[nt][1] - m0) * L2E);
                float p2 = exp2f((sc[nt][2] - m1) * L2E);
                float p3 = exp2f((sc[nt][3] - m1) * L2E);
                ps0 += p0 + p1;
                ps1 += p2 + p3;
                *(uint2*)(Pw + g*36 + nt*8 + 2*t)     = make_uint2(f2tf(p0), f2tf(p1));
                *(uint2*)(Pw + (g+8)*36 + nt*8 + 2*t) = make_uint2(f2tf(p2), f2tf(p3));
            }
            ps0 += __shfl_xor_sync(0xffffffffu, ps0, 1);
            ps0 += __shfl_xor_sync(0xffffffffu, ps0, 2);
            ps1 += __shfl_xor_sync(0xffffffffu, ps1, 1);
            ps1 += __shfl_xor_sync(0xffffffffu, ps1, 2);
            l0 = l0*c0f + ps0;
            l1 = l1*c1f + ps1;

            #pragma unroll
            for (int n = 0; n < 8; ++n) {
                o[n][0] *= c0f; o[n][1] *= c0f;
                o[n][2] *= c1f; o[n][3] *= c1f;
            }
            __syncwarp();

            #pragma unroll
            for (int ks = 0; ks < 4; ++ks) {
                unsigned af[4];
                af[0] = Pw[g*36 + ks*8 + t];
                af[1] = Pw[(g+8)*36 + ks*8 + t];
                af[2] = Pw[g*36 + ks*8 + t + 4];
                af[3] = Pw[(g+8)*36 + ks*8 + t + 4];
                #pragma unroll
                for (int n = 0; n < 8; ++n) {
                    unsigned bf[2];
                    bf[0] = Vs[(ks*8 + t)*PVV + n*8 + g];
                    bf[1] = Vs[(ks*8 + t + 4)*PVV + n*8 + g];
                    mma8(o[n], af, bf);
                }
            }
        }
        __syncthreads();
    }

    float i0 = 1.f / l0, i1 = 1.f / l1;
    #pragma unroll
    for (int n = 0; n < 8; ++n) {
        *(uint2*)(Op + (size_t)r0*HD + n*8 + 2*t) =
            make_uint2(f2tf(o[n][0]*i0), f2tf(o[n][1]*i0));
        *(uint2*)(Op + (size_t)r1*HD + n*8 + 2*t) =
            make_uint2(f2tf(o[n][2]*i1), f2tf(o[n][3]*i1));
    }
}

// ---------------------------------------------------------------------------
// Kernel 3: out = attn_out(gathered) @ w_proj (cp.async double buffer).
// ---------------------------------------------------------------------------
__global__ __launch_bounds__(256, 2) void proj_gemm(float* __restrict__ out)
{
    extern __shared__ unsigned sm[];
    unsigned* Asb[2] = { sm,            sm + 128*PA };
    unsigned* Bsb[2] = { sm + 2*128*PA, sm + 2*128*PA + 32*PB };

    const int tid  = threadIdx.x;
    const int lane = tid & 31;
    const int w    = tid >> 5;
    const int wm   = w >> 2;
    const int wn   = w & 3;
    const int g    = lane >> 2;
    const int t    = lane & 3;
    const int bm   = blockIdx.y, bn = blockIdx.x;

    float acc[4][4][4];
    #pragma unroll
    for (int i = 0; i < 4; ++i)
        #pragma unroll
        for (int j = 0; j < 4; ++j)
            #pragma unroll
            for (int q = 0; q < 4; ++q) acc[i][j][q] = 0.f;

    auto load_chunk = [&](int c, int s) {
        #pragma unroll
        for (int u = 0; u < 4; ++u) {
            int id  = tid + 256*u;
            int row = id >> 3, off = (id & 7) * 4;
            int kk = c*32 + off;
            int h = kk >> 6, d = kk & 63;
            int m = bm*128 + row;
            int b = m >> 8, tt = m & 255;
            cp16(Asb[s] + row*PA + off,
                 g_o + (((size_t)(b*NHEAD + h))*SEQ + tt)*HD + d);
            int br = id >> 5, bo = (id & 31) * 4;
            cp16(Bsb[s] + br*PB + bo,
                 g_wpt + (size_t)(c*32 + br)*NEMB + bn*128 + bo);
        }
        cp_commit();
    };

    load_chunk(0, 0);
    for (int c = 0; c < NCHUNK; ++c) {
        const int s = c & 1;
        if (c + 1 < NCHUNK) { load_chunk(c+1, s^1); cp_wait<1>(); }
        else                { cp_wait<0>(); }
        __syncthreads();

        const unsigned* A = Asb[s];
        const unsigned* B = Bsb[s];
        #pragma unroll
        for (int ks = 0; ks < 4; ++ks) {
            const int kk = ks*8 + t;
            unsigned af[4][4], bf[4][2];
            #pragma unroll
            for (int mf = 0; mf < 4; ++mf) {
                int r = wm*64 + mf*16 + g;
                af[mf][0] = A[r*PA + kk];
                af[mf][1] = A[(r+8)*PA + kk];
                af[mf][2] = A[r*PA + kk + 4];
                af[mf][3] = A[(r+8)*PA + kk + 4];
            }
            #pragma unroll
            for (int nf = 0; nf < 4; ++nf) {
                int n = wn*32 + nf*8 + g;
                bf[nf][0] = B[kk*PB + n];
                bf[nf][1] = B[(kk+4)*PB + n];
            }
            #pragma unroll
            for (int mf = 0; mf < 4; ++mf)
                #pragma unroll
                for (int nf = 0; nf < 4; ++nf)
                    mma8(acc[mf][nf], af[mf], bf[nf]);
        }
        __syncthreads();
    }

    #pragma unroll
    for (int mf = 0; mf < 4; ++mf) {
        int r0 = bm*128 + wm*64 + mf*16 + g;
        #pragma unroll
        for (int half = 0; half < 2; ++half) {
            int row = r0 + 8*half;
            #pragma unroll
            for (int nf = 0; nf < 4; ++nf) {
                int nn = bn*128 + wn*32 + nf*8 + 2*t;
                *(float2*)(out + (size_t)row*NEMB + nn) =
                    make_float2(acc[mf][nf][2*half], acc[mf][nf][2*half+1]);
            }
        }
    }
}

// ---------------------------------------------------------------------------
extern "C" void kernel_launch(void* const* d_in, const int* in_sizes, int n_in,
                              void* d_out, int out_size)
{
    const float* x      = (const float*)d_in[0];
    const float* w_attn = (const float*)d_in[1];
    const float* w_proj = (const float*)d_in[2];
    float* out = (float*)d_out;

    const int SMEM_GEMM = (2*128*PA + 2*32*PB) * 4;      // 71680 B
    const int SMEM_ATTN = ATTN_SMEM_WORDS * 4;            // 54272 B
    cudaFuncSetAttribute(qkv_gemm_rope,
        cudaFuncAttributeMaxDynamicSharedMemorySize, SMEM_GEMM);
    cudaFuncSetAttribute(proj_gemm,
        cudaFuncAttributeMaxDynamicSharedMemorySize, SMEM_GEMM);
    cudaFuncSetAttribute(attn_mma,
        cudaFuncAttributeMaxDynamicSharedMemorySize, SMEM_ATTN);

    const int NX4 = MTOT*NEMB/4;
    conv_tf32<<<(NX4 + 255)/256, 256>>>(x, w_attn, w_proj);

    dim3 g1(N_QKV/128, MTOT/128);   // (9, 128)
    qkv_gemm_rope<<<g1, 256, SMEM_GEMM>>>();

    dim3 g2(BH, 2);
    attn_mma<<<g2, 256, SMEM_ATTN>>>();

    dim3 g3(NEMB/128, MTOT/128);    // (3, 128)
    proj_gemm<<<g3, 256, SMEM_GEMM>>>(out);
}